// round 12
// baseline (speedup 1.0000x reference)
#include <cuda_runtime.h>
#include <cuda_fp16.h>
#include <cstdint>

#define C_IN    128
#define C_OUT   64
#define KOFF    27
#define M_PAIRS 100000
#define N_ROWS  100000
#define N_OUTP  200000
#define BN_EPS  1e-5f

// ---------------- device scratch (allocation-free) --------------------------
__device__ __half g_Xh[(size_t)N_ROWS * C_IN];            // 25.6 MB, L2-resident
// B pre-strided in smem image layout: [k][co][136 halves] (272 B rows)
__device__ __align__(256) __half g_Wsw[(size_t)KOFF * C_OUT * 136];
__device__ float g_sum[C_OUT], g_sumsq[C_OUT];

// ---------------- PTX helpers ----------------------------------------------
__device__ __forceinline__ uint32_t smem_u32(const void* p) {
    uint32_t a;
    asm("{ .reg .u64 t; cvta.to.shared.u64 t, %1; cvt.u32.u64 %0, t; }" : "=r"(a) : "l"(p));
    return a;
}
#define BULK_CP(dst, src, bytes, mbar) \
    asm volatile("cp.async.bulk.shared::cluster.global.mbarrier::complete_tx::bytes " \
        "[%0], [%1], %2, [%3];" :: "r"(dst), "l"(src), "r"(bytes), "r"(mbar) : "memory")

#define MBAR_INIT(a, c) \
    asm volatile("mbarrier.init.shared.b64 [%0], %1;" :: "r"(a), "r"(c) : "memory")
#define MBAR_EXPECT_TX(a, tx) \
    asm volatile("mbarrier.arrive.expect_tx.shared.b64 _, [%0], %1;" :: "r"(a), "r"(tx) : "memory")
#define MBAR_WAIT(a, ph) do {                                                   \
    asm volatile("{ .reg .pred P; WL%=:"                                        \
        " mbarrier.try_wait.parity.acquire.cta.shared::cta.b64 P, [%0], %1, 0x989680;" \
        " @P bra.uni WD%=; bra.uni WL%=; WD%=: }"                               \
        :: "r"(a), "r"(ph) : "memory");                                         \
} while (0)

#define LDMATRIX_X4(r, addr) \
    asm volatile("ldmatrix.sync.aligned.m8n8.x4.shared.b16 {%0,%1,%2,%3}, [%4];" \
        : "=r"((r)[0]), "=r"((r)[1]), "=r"((r)[2]), "=r"((r)[3]) : "r"(addr))

#define MMA16816(d, a, b0, b1) \
    asm volatile("mma.sync.aligned.m16n8k16.row.col.f32.f16.f16.f32 " \
        "{%0,%1,%2,%3}, {%4,%5,%6,%7}, {%8,%9}, {%0,%1,%2,%3};" \
        : "+f"((d)[0]), "+f"((d)[1]), "+f"((d)[2]), "+f"((d)[3]) \
        : "r"((a)[0]), "r"((a)[1]), "r"((a)[2]), "r"((a)[3]), "r"(b0), "r"(b1))

// ---------------- prep: x->fp16 + zero out | w->strided fp16 + zero stats ---
#define XBLKS 12500

__global__ void __launch_bounds__(256)
prep_kernel(const float* __restrict__ x,
            const float* __restrict__ w,
            float* __restrict__ out,
            int out_n4)
{
    const int gid = blockIdx.x;
    if (gid < XBLKS) {
        const int idx = gid * 256 + threadIdx.x;
        float4 v = ((const float4*)x)[idx];
        __half2* dst = (__half2*)(g_Xh + (size_t)idx * 4);
        dst[0] = __floats2half2_rn(v.x, v.y);
        dst[1] = __floats2half2_rn(v.z, v.w);
        if (idx < out_n4)
            ((float4*)out)[idx] = make_float4(0.f, 0.f, 0.f, 0.f);
    } else {
        const int j = (gid - XBLKS) * 256 + threadIdx.x;
        if (j < C_OUT) { g_sum[j] = 0.f; g_sumsq[j] = 0.f; }
        if (j < KOFF * C_IN * C_OUT) {
            const int k  = j / (C_IN * C_OUT);
            const int r  = j % (C_IN * C_OUT);
            const int ci = r / C_OUT, co = r % C_OUT;
            g_Wsw[(size_t)k * (C_OUT * 136) + co * 136 + ci] = __float2half_rn(w[j]);
        }
    }
}

// ---------------- fused gather(bulk) + HMMA + v4-RED scatter ----------------
// R11-proven shape: grid = (521, 27); block = 192 threads (6 warps).
// Epilogue change only: butterfly-repack fragments so each lane issues ONE
// red.v4 per fragment (2 ops per 32B sector instead of 4), halving the L2
// atomic op count. Mainloop byte-identical to R11.
#define PAIRS_BLK 192
#define ROWB      272
#define SM_MBAR0  0
#define SM_MBAR1  8
#define SM_A      32
#define SM_B      (SM_A + PAIRS_BLK * ROWB)     // 52256
#define B_BYTES   (64 * ROWB)                   // 17408
#define SMEM_FUSED (SM_B + B_BYTES)             // 69664

__global__ void __launch_bounds__(PAIRS_BLK)
fused_kernel(const int* __restrict__ in_map,
             const int* __restrict__ out_map,
             float* __restrict__ out)
{
    extern __shared__ char smem[];
    const uint32_t sbase = smem_u32(smem);
    const uint32_t abase = sbase + SM_A;
    const uint32_t bbase = sbase + SM_B;

    const int t    = threadIdx.x;
    const int lane = t & 31;
    const int w    = t >> 5;
    const int k    = blockIdx.y;

    // ---- pair indices (thread t owns pair-row t) ----
    const int p     = blockIdx.x * PAIRS_BLK + t;
    const int valid = (p < M_PAIRS);
    const int pc    = valid ? p : (M_PAIRS - 1);
    const int im    = in_map [k * M_PAIRS + pc];
    const int om    = valid ? out_map[k * M_PAIRS + pc] : -1;

    if (t == 0) { MBAR_INIT(sbase + SM_MBAR0, 1); MBAR_INIT(sbase + SM_MBAR1, 1); }
    __syncthreads();
    if (t == 0) MBAR_EXPECT_TX(sbase + SM_MBAR0, 96 * 256 + B_BYTES);
    if (t == 1) MBAR_EXPECT_TX(sbase + SM_MBAR1, 96 * 256);

    // ---- gather A: one 256B bulk per row; B: ONE 17408B bulk (t==0) ----
    const uint32_t mybar = sbase + (t < 96 ? SM_MBAR0 : SM_MBAR1);
    BULK_CP(abase + t * ROWB, g_Xh + (size_t)im * C_IN, 256, mybar);
    if (t == 0)
        BULK_CP(bbase, g_Wsw + (size_t)k * (C_OUT * 136), B_BYTES,
                sbase + SM_MBAR0);

    MBAR_WAIT(sbase + SM_MBAR0, 0);
    if (w >= 3) MBAR_WAIT(sbase + SM_MBAR1, 0);

    // ---- MMA mainloop: warp w owns rows [32w, 32w+32), cols 0..63 ----
    float d[2][8][4];
    #pragma unroll
    for (int mt = 0; mt < 2; ++mt)
        #pragma unroll
        for (int nt = 0; nt < 8; ++nt)
            #pragma unroll
            for (int j = 0; j < 4; ++j) d[mt][nt][j] = 0.f;

    #pragma unroll
    for (int kc = 0; kc < 8; ++kc) {
        uint32_t a_frag[2][4];
        #pragma unroll
        for (int mt = 0; mt < 2; ++mt) {
            int row = w * 32 + mt * 16 + (lane & 15);
            int ch  = kc * 2 + (lane >> 4);
            LDMATRIX_X4(a_frag[mt], abase + row * ROWB + ch * 16);
        }
        uint32_t b_frag[4][4];
        #pragma unroll
        for (int nt2 = 0; nt2 < 4; ++nt2) {
            int n  = nt2 * 16 + ((lane >> 4) << 3) + (lane & 7);
            int ch = kc * 2 + ((lane >> 3) & 1);
            LDMATRIX_X4(b_frag[nt2], bbase + n * ROWB + ch * 16);
        }
        #pragma unroll
        for (int mt = 0; mt < 2; ++mt)
            #pragma unroll
            for (int nt = 0; nt < 8; ++nt)
                MMA16816(d[mt][nt], a_frag[mt],
                         b_frag[nt >> 1][(nt & 1) * 2],
                         b_frag[nt >> 1][(nt & 1) * 2 + 1]);
    }

    // ---- scatter-add: butterfly repack -> one red.v4 per fragment ----
    // Fragment group (4 lanes, same lane>>2) holds rows r, r+8, cols 0..7.
    // Exchange with lane^1: even lane -> row r cols {c..c+3},
    // odd lane -> row r+8 cols {c..c+3}, c = (lane>>1 & 1)*4.
    {
        const int  jm    = lane & 3;
        const bool evenl = (lane & 1) == 0;
        const int  cbase = (jm >> 1) * 4;
        #pragma unroll
        for (int mt = 0; mt < 2; ++mt) {
            const int src = mt * 16 + (lane >> 2);
            const int om0 = __shfl_sync(0xffffffffu, om, src);
            const int om1 = __shfl_sync(0xffffffffu, om, src + 8);
            const int omr = evenl ? om0 : om1;
            float* dst = out + (size_t)(omr < 0 ? 0 : omr) * C_OUT + cbase;
            #pragma unroll
            for (int nt = 0; nt < 8; ++nt) {
                const float va = evenl ? d[mt][nt][2] : d[mt][nt][0];
                const float vb = evenl ? d[mt][nt][3] : d[mt][nt][1];
                const float ra = __shfl_xor_sync(0xffffffffu, va, 1);
                const float rb = __shfl_xor_sync(0xffffffffu, vb, 1);
                const float v0 = evenl ? d[mt][nt][0] : ra;
                const float v1 = evenl ? d[mt][nt][1] : rb;
                const float v2 = evenl ? ra : d[mt][nt][2];
                const float v3 = evenl ? rb : d[mt][nt][3];
                if (omr >= 0)
                    asm volatile("red.global.add.v4.f32 [%0], {%1,%2,%3,%4};"
                                 :: "l"(dst + nt * 8),
                                    "f"(v0), "f"(v1), "f"(v2), "f"(v3)
                                 : "memory");
            }
        }
    }
}

// ---------------- BN stats: float4 loads, one sync (R10-proven) -------------
__global__ void __launch_bounds__(256)
stats_kernel(const float* __restrict__ out)
{
    __shared__ float ss[16 * C_OUT], sq[16 * C_OUT];   // 2 x 4 KB
    const int t   = threadIdx.x;
    const int c4  = (t & 15) * 4;
    const int rep = t >> 4;
    float4 s = make_float4(0.f, 0.f, 0.f, 0.f);
    float4 q = make_float4(0.f, 0.f, 0.f, 0.f);
    for (int row = blockIdx.x * 16 + rep; row < N_OUTP; row += gridDim.x * 16) {
        const float4 v = *(const float4*)(out + (size_t)row * C_OUT + c4);
        s.x += v.x; q.x = fmaf(v.x, v.x, q.x);
        s.y += v.y; q.y = fmaf(v.y, v.y, q.y);
        s.z += v.z; q.z = fmaf(v.z, v.z, q.z);
        s.w += v.w; q.w = fmaf(v.w, v.w, q.w);
    }
    *(float4*)&ss[rep * C_OUT + c4] = s;
    *(float4*)&sq[rep * C_OUT + c4] = q;
    __syncthreads();
    if (t < C_OUT) {
        float as = 0.f, aq = 0.f;
        #pragma unroll
        for (int r = 0; r < 16; ++r) {
            as += ss[r * C_OUT + t];
            aq += sq[r * C_OUT + t];
        }
        atomicAdd(&g_sum[t],   as);
        atomicAdd(&g_sumsq[t], aq);
    }
}

// ---------------- normalize + ReLU (finalize folded in) ---------------------
__global__ void __launch_bounds__(256)
normalize_kernel(float* __restrict__ out,
                 const float* __restrict__ gamma,
                 const float* __restrict__ beta)
{
    __shared__ float sc[C_OUT], bs[C_OUT];
    if (threadIdx.x < C_OUT) {
        const int c = threadIdx.x;
        const float inv_n = 1.0f / (float)N_OUTP;
        const float mean = g_sum[c] * inv_n;
        const float var  = g_sumsq[c] * inv_n - mean * mean;
        const float s    = gamma[c] * rsqrtf(var + BN_EPS);
        sc[c] = s;
        bs[c] = beta[c] - mean * s;
    }
    __syncthreads();
    const int total4 = N_OUTP * C_OUT / 4;
    for (int i = blockIdx.x * blockDim.x + threadIdx.x; i < total4;
         i += gridDim.x * blockDim.x) {
        float4 v = ((float4*)out)[i];
        const int c0 = (i * 4) & 63;
        v.x = fmaxf(fmaf(v.x, sc[c0 + 0], bs[c0 + 0]), 0.f);
        v.y = fmaxf(fmaf(v.y, sc[c0 + 1], bs[c0 + 1]), 0.f);
        v.z = fmaxf(fmaf(v.z, sc[c0 + 2], bs[c0 + 2]), 0.f);
        v.w = fmaxf(fmaf(v.w, sc[c0 + 3], bs[c0 + 3]), 0.f);
        ((float4*)out)[i] = v;
    }
}

// ---------------- launch ----------------------------------------------------
extern "C" void kernel_launch(void* const* d_in, const int* in_sizes, int n_in,
                              void* d_out, int out_size)
{
    const float* x       = (const float*)d_in[0];
    const float* weight  = (const float*)d_in[1];
    const float* gamma   = (const float*)d_in[2];
    const float* beta    = (const float*)d_in[3];
    const int*   in_map  = (const int*)d_in[4];
    const int*   out_map = (const int*)d_in[5];
    float*       out     = (float*)d_out;

    cudaFuncSetAttribute(fused_kernel, cudaFuncAttributeMaxDynamicSharedMemorySize,
                         SMEM_FUSED);

    const int wblks = (KOFF * C_IN * C_OUT + 255) / 256;       // 864
    prep_kernel<<<XBLKS + wblks, 256>>>(x, weight, out, out_size / 4);

    {
        dim3 grid((M_PAIRS + PAIRS_BLK - 1) / PAIRS_BLK, KOFF);
        fused_kernel<<<grid, PAIRS_BLK, SMEM_FUSED>>>(in_map, out_map, out);
    }

    stats_kernel<<<1184, 256>>>(out);
    normalize_kernel<<<2048, 256>>>(out, gamma, beta);
}

// round 13
// speedup vs baseline: 1.0086x; 1.0086x over previous
#include <cuda_runtime.h>
#include <cuda_fp16.h>
#include <cstdint>

#define C_IN    128
#define C_OUT   64
#define KOFF    27
#define M_PAIRS 100000
#define N_ROWS  100000
#define N_OUTP  200000
#define BN_EPS  1e-5f

// ---------------- device scratch (allocation-free) --------------------------
__device__ __half g_Xh[(size_t)N_ROWS * C_IN];            // 25.6 MB, L2-resident
// B pre-strided in smem image layout: [k][co][136 halves] (272 B rows)
__device__ __align__(256) __half g_Wsw[(size_t)KOFF * C_OUT * 136];
__device__ float g_sum[C_OUT], g_sumsq[C_OUT];

// ---------------- PTX helpers ----------------------------------------------
__device__ __forceinline__ uint32_t smem_u32(const void* p) {
    uint32_t a;
    asm("{ .reg .u64 t; cvta.to.shared.u64 t, %1; cvt.u32.u64 %0, t; }" : "=r"(a) : "l"(p));
    return a;
}
#define BULK_CP(dst, src, bytes, mbar) \
    asm volatile("cp.async.bulk.shared::cluster.global.mbarrier::complete_tx::bytes " \
        "[%0], [%1], %2, [%3];" :: "r"(dst), "l"(src), "r"(bytes), "r"(mbar) : "memory")

#define MBAR_INIT(a, c) \
    asm volatile("mbarrier.init.shared.b64 [%0], %1;" :: "r"(a), "r"(c) : "memory")
#define MBAR_EXPECT_TX(a, tx) \
    asm volatile("mbarrier.arrive.expect_tx.shared.b64 _, [%0], %1;" :: "r"(a), "r"(tx) : "memory")
#define MBAR_WAIT(a, ph) do {                                                   \
    asm volatile("{ .reg .pred P; WL%=:"                                        \
        " mbarrier.try_wait.parity.acquire.cta.shared::cta.b64 P, [%0], %1, 0x989680;" \
        " @P bra.uni WD%=; bra.uni WL%=; WD%=: }"                               \
        :: "r"(a), "r"(ph) : "memory");                                         \
} while (0)

#define LDMATRIX_X4(r, addr) \
    asm volatile("ldmatrix.sync.aligned.m8n8.x4.shared.b16 {%0,%1,%2,%3}, [%4];" \
        : "=r"((r)[0]), "=r"((r)[1]), "=r"((r)[2]), "=r"((r)[3]) : "r"(addr))

#define MMA16816(d, a, b0, b1) \
    asm volatile("mma.sync.aligned.m16n8k16.row.col.f32.f16.f16.f32 " \
        "{%0,%1,%2,%3}, {%4,%5,%6,%7}, {%8,%9}, {%0,%1,%2,%3};" \
        : "+f"((d)[0]), "+f"((d)[1]), "+f"((d)[2]), "+f"((d)[3]) \
        : "r"((a)[0]), "r"((a)[1]), "r"((a)[2]), "r"((a)[3]), "r"(b0), "r"(b1))

// ---------------- prep: x->fp16 + zero out | w->strided fp16 + zero stats ---
// blocks [0, 12500): convert one x float4 AND zero the matching out float4.
// blocks [12500, 13364): w -> g_Wsw smem-image layout + zero stats.
#define XBLKS 12500

__global__ void __launch_bounds__(256)
prep_kernel(const float* __restrict__ x,
            const float* __restrict__ w,
            float* __restrict__ out,
            int out_n4)
{
    const int gid = blockIdx.x;
    if (gid < XBLKS) {
        const int idx = gid * 256 + threadIdx.x;
        float4 v = ((const float4*)x)[idx];
        __half2* dst = (__half2*)(g_Xh + (size_t)idx * 4);
        dst[0] = __floats2half2_rn(v.x, v.y);
        dst[1] = __floats2half2_rn(v.z, v.w);
        if (idx < out_n4)
            ((float4*)out)[idx] = make_float4(0.f, 0.f, 0.f, 0.f);
    } else {
        const int j = (gid - XBLKS) * 256 + threadIdx.x;
        if (j < C_OUT) { g_sum[j] = 0.f; g_sumsq[j] = 0.f; }
        if (j < KOFF * C_IN * C_OUT) {
            const int k  = j / (C_IN * C_OUT);
            const int r  = j % (C_IN * C_OUT);
            const int ci = r / C_OUT, co = r % C_OUT;
            // smem image: row co is 136 halves (272 B), first 128 carry data
            g_Wsw[(size_t)k * (C_OUT * 136) + co * 136 + ci] = __float2half_rn(w[j]);
        }
    }
}

// ---------------- fused gather(bulk) + HMMA + direct-frag scatter -----------
// Converged shape: grid = (521, 27); block = 192 threads (6 warps), 3 CTAs/SM
// (regfile: 96 regs x 576 thr; smem: 3 x 69.7 KB — both at their caps).
// Tile: 192 pairs x 64 out-channels, K = 128. Warp w owns rows [32w, 32w+32).
// Split barriers overlap second-half gather with first-half MMA; B lands via
// ONE 17408B bulk-cp from the pre-strided g_Wsw image; scatter goes straight
// from MMA fragments as coalesced 32B-sector red.v2 ops.
#define PAIRS_BLK 192
#define ROWB      272
#define SM_MBAR0  0
#define SM_MBAR1  8
#define SM_A      32
#define SM_B      (SM_A + PAIRS_BLK * ROWB)     // 52256
#define B_BYTES   (64 * ROWB)                   // 17408
#define SMEM_FUSED (SM_B + B_BYTES)             // 69664

__global__ void __launch_bounds__(PAIRS_BLK)
fused_kernel(const int* __restrict__ in_map,
             const int* __restrict__ out_map,
             float* __restrict__ out)
{
    extern __shared__ char smem[];
    const uint32_t sbase = smem_u32(smem);
    const uint32_t abase = sbase + SM_A;
    const uint32_t bbase = sbase + SM_B;

    const int t    = threadIdx.x;
    const int lane = t & 31;
    const int w    = t >> 5;
    const int k    = blockIdx.y;

    // ---- pair indices (thread t owns pair-row t) ----
    const int p     = blockIdx.x * PAIRS_BLK + t;
    const int valid = (p < M_PAIRS);
    const int pc    = valid ? p : (M_PAIRS - 1);
    const int im    = in_map [k * M_PAIRS + pc];
    const int om    = valid ? out_map[k * M_PAIRS + pc] : -1;

    if (t == 0) { MBAR_INIT(sbase + SM_MBAR0, 1); MBAR_INIT(sbase + SM_MBAR1, 1); }
    __syncthreads();
    if (t == 0) MBAR_EXPECT_TX(sbase + SM_MBAR0, 96 * 256 + B_BYTES);
    if (t == 1) MBAR_EXPECT_TX(sbase + SM_MBAR1, 96 * 256);

    // ---- gather A: one 256B bulk per row; B: ONE 17408B bulk (t==0) ----
    const uint32_t mybar = sbase + (t < 96 ? SM_MBAR0 : SM_MBAR1);
    BULK_CP(abase + t * ROWB, g_Xh + (size_t)im * C_IN, 256, mybar);
    if (t == 0)
        BULK_CP(bbase, g_Wsw + (size_t)k * (C_OUT * 136), B_BYTES,
                sbase + SM_MBAR0);

    MBAR_WAIT(sbase + SM_MBAR0, 0);
    if (w >= 3) MBAR_WAIT(sbase + SM_MBAR1, 0);

    // ---- MMA mainloop: warp w owns rows [32w, 32w+32), cols 0..63 ----
    float d[2][8][4];
    #pragma unroll
    for (int mt = 0; mt < 2; ++mt)
        #pragma unroll
        for (int nt = 0; nt < 8; ++nt)
            #pragma unroll
            for (int j = 0; j < 4; ++j) d[mt][nt][j] = 0.f;

    #pragma unroll
    for (int kc = 0; kc < 8; ++kc) {
        uint32_t a_frag[2][4];
        #pragma unroll
        for (int mt = 0; mt < 2; ++mt) {
            int row = w * 32 + mt * 16 + (lane & 15);
            int ch  = kc * 2 + (lane >> 4);
            LDMATRIX_X4(a_frag[mt], abase + row * ROWB + ch * 16);
        }
        uint32_t b_frag[4][4];
        #pragma unroll
        for (int nt2 = 0; nt2 < 4; ++nt2) {
            int n  = nt2 * 16 + ((lane >> 4) << 3) + (lane & 7);
            int ch = kc * 2 + ((lane >> 3) & 1);
            LDMATRIX_X4(b_frag[nt2], bbase + n * ROWB + ch * 16);
        }
        #pragma unroll
        for (int mt = 0; mt < 2; ++mt)
            #pragma unroll
            for (int nt = 0; nt < 8; ++nt)
                MMA16816(d[mt][nt], a_frag[mt],
                         b_frag[nt >> 1][(nt & 1) * 2],
                         b_frag[nt >> 1][(nt & 1) * 2 + 1]);
    }

    // ---- scatter-add straight from fragments; out rows fetched via shfl ----
    // fragment (mt, nt): rows r = mt*16+(lane>>2) (+8) within this warp;
    // 4 lanes with equal lane>>2 cover one contiguous 32B sector of one row.
    #pragma unroll
    for (int mt = 0; mt < 2; ++mt) {
        const int src  = mt * 16 + (lane >> 2);
        const int om0  = __shfl_sync(0xffffffffu, om, src);
        const int om1  = __shfl_sync(0xffffffffu, om, src + 8);
        float* dst0 = out + (size_t)om0 * C_OUT + (lane & 3) * 2;
        float* dst1 = out + (size_t)om1 * C_OUT + (lane & 3) * 2;
        #pragma unroll
        for (int nt = 0; nt < 8; ++nt) {
            if (om0 >= 0)
                asm volatile("red.global.add.v2.f32 [%0], {%1,%2};"
                             :: "l"(dst0 + nt * 8), "f"(d[mt][nt][0]), "f"(d[mt][nt][1])
                             : "memory");
            if (om1 >= 0)
                asm volatile("red.global.add.v2.f32 [%0], {%1,%2};"
                             :: "l"(dst1 + nt * 8), "f"(d[mt][nt][2]), "f"(d[mt][nt][3])
                             : "memory");
        }
    }
}

// ---------------- BN stats: float4 loads, one sync --------------------------
__global__ void __launch_bounds__(256)
stats_kernel(const float* __restrict__ out)
{
    __shared__ float ss[16 * C_OUT], sq[16 * C_OUT];   // 2 x 4 KB
    const int t   = threadIdx.x;
    const int c4  = (t & 15) * 4;
    const int rep = t >> 4;
    float4 s = make_float4(0.f, 0.f, 0.f, 0.f);
    float4 q = make_float4(0.f, 0.f, 0.f, 0.f);
    for (int row = blockIdx.x * 16 + rep; row < N_OUTP; row += gridDim.x * 16) {
        const float4 v = *(const float4*)(out + (size_t)row * C_OUT + c4);
        s.x += v.x; q.x = fmaf(v.x, v.x, q.x);
        s.y += v.y; q.y = fmaf(v.y, v.y, q.y);
        s.z += v.z; q.z = fmaf(v.z, v.z, q.z);
        s.w += v.w; q.w = fmaf(v.w, v.w, q.w);
    }
    *(float4*)&ss[rep * C_OUT + c4] = s;
    *(float4*)&sq[rep * C_OUT + c4] = q;
    __syncthreads();
    if (t < C_OUT) {
        float as = 0.f, aq = 0.f;
        #pragma unroll
        for (int r = 0; r < 16; ++r) {
            as += ss[r * C_OUT + t];
            aq += sq[r * C_OUT + t];
        }
        atomicAdd(&g_sum[t],   as);
        atomicAdd(&g_sumsq[t], aq);
    }
}

// ---------------- normalize + ReLU (finalize folded in) ---------------------
__global__ void __launch_bounds__(256)
normalize_kernel(float* __restrict__ out,
                 const float* __restrict__ gamma,
                 const float* __restrict__ beta)
{
    __shared__ float sc[C_OUT], bs[C_OUT];
    if (threadIdx.x < C_OUT) {
        const int c = threadIdx.x;
        const float inv_n = 1.0f / (float)N_OUTP;
        const float mean = g_sum[c] * inv_n;
        const float var  = g_sumsq[c] * inv_n - mean * mean;
        const float s    = gamma[c] * rsqrtf(var + BN_EPS);
        sc[c] = s;
        bs[c] = beta[c] - mean * s;
    }
    __syncthreads();
    const int total4 = N_OUTP * C_OUT / 4;
    for (int i = blockIdx.x * blockDim.x + threadIdx.x; i < total4;
         i += gridDim.x * blockDim.x) {
        float4 v = ((float4*)out)[i];
        const int c0 = (i * 4) & 63;
        v.x = fmaxf(fmaf(v.x, sc[c0 + 0], bs[c0 + 0]), 0.f);
        v.y = fmaxf(fmaf(v.y, sc[c0 + 1], bs[c0 + 1]), 0.f);
        v.z = fmaxf(fmaf(v.z, sc[c0 + 2], bs[c0 + 2]), 0.f);
        v.w = fmaxf(fmaf(v.w, sc[c0 + 3], bs[c0 + 3]), 0.f);
        ((float4*)out)[i] = v;
    }
}

// ---------------- launch ----------------------------------------------------
extern "C" void kernel_launch(void* const* d_in, const int* in_sizes, int n_in,
                              void* d_out, int out_size)
{
    const float* x       = (const float*)d_in[0];
    const float* weight  = (const float*)d_in[1];
    const float* gamma   = (const float*)d_in[2];
    const float* beta    = (const float*)d_in[3];
    const int*   in_map  = (const int*)d_in[4];
    const int*   out_map = (const int*)d_in[5];
    float*       out     = (float*)d_out;

    cudaFuncSetAttribute(fused_kernel, cudaFuncAttributeMaxDynamicSharedMemorySize,
                         SMEM_FUSED);

    const int wblks = (KOFF * C_IN * C_OUT + 255) / 256;       // 864
    prep_kernel<<<XBLKS + wblks, 256>>>(x, weight, out, out_size / 4);

    {
        dim3 grid((M_PAIRS + PAIRS_BLK - 1) / PAIRS_BLK, KOFF);
        fused_kernel<<<grid, PAIRS_BLK, SMEM_FUSED>>>(in_map, out_map, out);
    }

    stats_kernel<<<1184, 256>>>(out);
    normalize_kernel<<<2048, 256>>>(out, gamma, beta);
}

// round 15
// speedup vs baseline: 1.2311x; 1.2206x over previous
#include <cuda_runtime.h>
#include <cuda_fp16.h>
#include <cstdint>

#define C_IN    128
#define C_OUT   64
#define KOFF    27
#define M_PAIRS 100000
#define N_ROWS  100000
#define N_OUTP  200000
#define BN_EPS  1e-5f

// ---------------- device scratch (allocation-free) --------------------------
__device__ __half g_Xh[(size_t)N_ROWS * C_IN];            // 25.6 MB, L2-resident
// B pre-strided in smem image layout: [k][co][136 halves] (272 B rows)
__device__ __align__(256) __half g_Wsw[(size_t)KOFF * C_OUT * 136];
// fp16 accumulation buffer for the conv output (halves RED/stats traffic)
__device__ __half g_Yh[(size_t)N_OUTP * C_OUT];           // 25.6 MB
__device__ float g_sum[C_OUT], g_sumsq[C_OUT];

// ---------------- PTX helpers ----------------------------------------------
__device__ __forceinline__ uint32_t smem_u32(const void* p) {
    uint32_t a;
    asm("{ .reg .u64 t; cvta.to.shared.u64 t, %1; cvt.u32.u64 %0, t; }" : "=r"(a) : "l"(p));
    return a;
}
#define BULK_CP(dst, src, bytes, mbar) \
    asm volatile("cp.async.bulk.shared::cluster.global.mbarrier::complete_tx::bytes " \
        "[%0], [%1], %2, [%3];" :: "r"(dst), "l"(src), "r"(bytes), "r"(mbar) : "memory")

#define MBAR_INIT(a, c) \
    asm volatile("mbarrier.init.shared.b64 [%0], %1;" :: "r"(a), "r"(c) : "memory")
#define MBAR_EXPECT_TX(a, tx) \
    asm volatile("mbarrier.arrive.expect_tx.shared.b64 _, [%0], %1;" :: "r"(a), "r"(tx) : "memory")
#define MBAR_WAIT(a, ph) do {                                                   \
    asm volatile("{ .reg .pred P; WL%=:"                                        \
        " mbarrier.try_wait.parity.acquire.cta.shared::cta.b64 P, [%0], %1, 0x989680;" \
        " @P bra.uni WD%=; bra.uni WL%=; WD%=: }"                               \
        :: "r"(a), "r"(ph) : "memory");                                         \
} while (0)

#define LDMATRIX_X4(r, addr) \
    asm volatile("ldmatrix.sync.aligned.m8n8.x4.shared.b16 {%0,%1,%2,%3}, [%4];" \
        : "=r"((r)[0]), "=r"((r)[1]), "=r"((r)[2]), "=r"((r)[3]) : "r"(addr))

#define MMA16816(d, a, b0, b1) \
    asm volatile("mma.sync.aligned.m16n8k16.row.col.f32.f16.f16.f32 " \
        "{%0,%1,%2,%3}, {%4,%5,%6,%7}, {%8,%9}, {%0,%1,%2,%3};" \
        : "+f"((d)[0]), "+f"((d)[1]), "+f"((d)[2]), "+f"((d)[3]) \
        : "r"((a)[0]), "r"((a)[1]), "r"((a)[2]), "r"((a)[3]), "r"(b0), "r"(b1))

#define RED_F16X2(addr, h2) \
    asm volatile("red.global.add.noftz.f16x2 [%0], %1;" \
        :: "l"(addr), "r"(h2) : "memory")

__device__ __forceinline__ uint32_t pack_h2(float a, float b) {
    __half2 h = __floats2half2_rn(a, b);      // lo = a, hi = b
    return *(uint32_t*)&h;
}

// ---------------- prep: x->fp16 + zero g_Yh | w->strided fp16 + stats -------
// blocks [0, 12500): convert one x float4; threads with idx < 1.6M also zero
// one 16B chunk of g_Yh (25.6 MB total).
// blocks [12500, 13364): w -> g_Wsw smem-image layout + zero stats.
#define XBLKS 12500
#define YH_N4 ((int)((size_t)N_OUTP * C_OUT / 8))   // 1.6M 16B chunks

__global__ void __launch_bounds__(256)
prep_kernel(const float* __restrict__ x,
            const float* __restrict__ w)
{
    const int gid = blockIdx.x;
    if (gid < XBLKS) {
        const int idx = gid * 256 + threadIdx.x;
        float4 v = ((const float4*)x)[idx];
        __half2* dst = (__half2*)(g_Xh + (size_t)idx * 4);
        dst[0] = __floats2half2_rn(v.x, v.y);
        dst[1] = __floats2half2_rn(v.z, v.w);
        if (idx < YH_N4)
            ((float4*)g_Yh)[idx] = make_float4(0.f, 0.f, 0.f, 0.f);
    } else {
        const int j = (gid - XBLKS) * 256 + threadIdx.x;
        if (j < C_OUT) { g_sum[j] = 0.f; g_sumsq[j] = 0.f; }
        if (j < KOFF * C_IN * C_OUT) {
            const int k  = j / (C_IN * C_OUT);
            const int r  = j % (C_IN * C_OUT);
            const int ci = r / C_OUT, co = r % C_OUT;
            g_Wsw[(size_t)k * (C_OUT * 136) + co * 136 + ci] = __float2half_rn(w[j]);
        }
    }
}

// ---------------- fused gather(bulk) + HMMA + fp16-RED scatter --------------
// R11-proven shape: grid = (521, 27); block = 192 threads (6 warps).
// ONLY change vs R11: scatter targets g_Yh via red.f16x2 (4B ops, same count,
// half the atomic bytes). Mainloop byte-identical.
#define PAIRS_BLK 192
#define ROWB      272
#define SM_MBAR0  0
#define SM_MBAR1  8
#define SM_A      32
#define SM_B      (SM_A + PAIRS_BLK * ROWB)     // 52256
#define B_BYTES   (64 * ROWB)                   // 17408
#define SMEM_FUSED (SM_B + B_BYTES)             // 69664

__global__ void __launch_bounds__(PAIRS_BLK)
fused_kernel(const int* __restrict__ in_map,
             const int* __restrict__ out_map)
{
    extern __shared__ char smem[];
    const uint32_t sbase = smem_u32(smem);
    const uint32_t abase = sbase + SM_A;
    const uint32_t bbase = sbase + SM_B;

    const int t    = threadIdx.x;
    const int lane = t & 31;
    const int w    = t >> 5;
    const int k    = blockIdx.y;

    // ---- pair indices (thread t owns pair-row t) ----
    const int p     = blockIdx.x * PAIRS_BLK + t;
    const int valid = (p < M_PAIRS);
    const int pc    = valid ? p : (M_PAIRS - 1);
    const int im    = in_map [k * M_PAIRS + pc];
    const int om    = valid ? out_map[k * M_PAIRS + pc] : -1;

    if (t == 0) { MBAR_INIT(sbase + SM_MBAR0, 1); MBAR_INIT(sbase + SM_MBAR1, 1); }
    __syncthreads();
    if (t == 0) MBAR_EXPECT_TX(sbase + SM_MBAR0, 96 * 256 + B_BYTES);
    if (t == 1) MBAR_EXPECT_TX(sbase + SM_MBAR1, 96 * 256);

    // ---- gather A: one 256B bulk per row; B: ONE 17408B bulk (t==0) ----
    const uint32_t mybar = sbase + (t < 96 ? SM_MBAR0 : SM_MBAR1);
    BULK_CP(abase + t * ROWB, g_Xh + (size_t)im * C_IN, 256, mybar);
    if (t == 0)
        BULK_CP(bbase, g_Wsw + (size_t)k * (C_OUT * 136), B_BYTES,
                sbase + SM_MBAR0);

    MBAR_WAIT(sbase + SM_MBAR0, 0);
    if (w >= 3) MBAR_WAIT(sbase + SM_MBAR1, 0);

    // ---- MMA mainloop: warp w owns rows [32w, 32w+32), cols 0..63 ----
    float d[2][8][4];
    #pragma unroll
    for (int mt = 0; mt < 2; ++mt)
        #pragma unroll
        for (int nt = 0; nt < 8; ++nt)
            #pragma unroll
            for (int j = 0; j < 4; ++j) d[mt][nt][j] = 0.f;

    #pragma unroll
    for (int kc = 0; kc < 8; ++kc) {
        uint32_t a_frag[2][4];
        #pragma unroll
        for (int mt = 0; mt < 2; ++mt) {
            int row = w * 32 + mt * 16 + (lane & 15);
            int ch  = kc * 2 + (lane >> 4);
            LDMATRIX_X4(a_frag[mt], abase + row * ROWB + ch * 16);
        }
        uint32_t b_frag[4][4];
        #pragma unroll
        for (int nt2 = 0; nt2 < 4; ++nt2) {
            int n  = nt2 * 16 + ((lane >> 4) << 3) + (lane & 7);
            int ch = kc * 2 + ((lane >> 3) & 1);
            LDMATRIX_X4(b_frag[nt2], bbase + n * ROWB + ch * 16);
        }
        #pragma unroll
        for (int mt = 0; mt < 2; ++mt)
            #pragma unroll
            for (int nt = 0; nt < 8; ++nt)
                MMA16816(d[mt][nt], a_frag[mt],
                         b_frag[nt >> 1][(nt & 1) * 2],
                         b_frag[nt >> 1][(nt & 1) * 2 + 1]);
    }

    // ---- scatter-add from fragments as fp16x2 reductions ----
    // same structure/addressing as R11, half the atomic bytes.
    #pragma unroll
    for (int mt = 0; mt < 2; ++mt) {
        const int src  = mt * 16 + (lane >> 2);
        const int om0  = __shfl_sync(0xffffffffu, om, src);
        const int om1  = __shfl_sync(0xffffffffu, om, src + 8);
        __half* dst0 = g_Yh + (size_t)om0 * C_OUT + (lane & 3) * 2;
        __half* dst1 = g_Yh + (size_t)om1 * C_OUT + (lane & 3) * 2;
        #pragma unroll
        for (int nt = 0; nt < 8; ++nt) {
            if (om0 >= 0)
                RED_F16X2(dst0 + nt * 8, pack_h2(d[mt][nt][0], d[mt][nt][1]));
            if (om1 >= 0)
                RED_F16X2(dst1 + nt * 8, pack_h2(d[mt][nt][2], d[mt][nt][3]));
        }
    }
}

// ---------------- BN stats: read fp16 buffer, accumulate f32 ----------------
__global__ void __launch_bounds__(256)
stats_kernel()
{
    __shared__ float ss[16 * C_OUT], sq[16 * C_OUT];   // 2 x 4 KB
    const int t   = threadIdx.x;
    const int c4  = (t & 15) * 4;
    const int rep = t >> 4;
    float4 s = make_float4(0.f, 0.f, 0.f, 0.f);
    float4 q = make_float4(0.f, 0.f, 0.f, 0.f);
    for (int row = blockIdx.x * 16 + rep; row < N_OUTP; row += gridDim.x * 16) {
        const uint2 u = *(const uint2*)(g_Yh + (size_t)row * C_OUT + c4);
        const float2 v01 = __half22float2(*(const __half2*)&u.x);
        const float2 v23 = __half22float2(*(const __half2*)&u.y);
        s.x += v01.x; q.x = fmaf(v01.x, v01.x, q.x);
        s.y += v01.y; q.y = fmaf(v01.y, v01.y, q.y);
        s.z += v23.x; q.z = fmaf(v23.x, v23.x, q.z);
        s.w += v23.y; q.w = fmaf(v23.y, v23.y, q.w);
    }
    *(float4*)&ss[rep * C_OUT + c4] = s;
    *(float4*)&sq[rep * C_OUT + c4] = q;
    __syncthreads();
    if (t < C_OUT) {
        float as = 0.f, aq = 0.f;
        #pragma unroll
        for (int r = 0; r < 16; ++r) {
            as += ss[r * C_OUT + t];
            aq += sq[r * C_OUT + t];
        }
        atomicAdd(&g_sum[t],   as);
        atomicAdd(&g_sumsq[t], aq);
    }
}

// ---------------- normalize + ReLU: fp16 in, f32 out ------------------------
__global__ void __launch_bounds__(256)
normalize_kernel(float* __restrict__ out,
                 const float* __restrict__ gamma,
                 const float* __restrict__ beta)
{
    __shared__ float sc[C_OUT], bs[C_OUT];
    if (threadIdx.x < C_OUT) {
        const int c = threadIdx.x;
        const float inv_n = 1.0f / (float)N_OUTP;
        const float mean = g_sum[c] * inv_n;
        const float var  = g_sumsq[c] * inv_n - mean * mean;
        const float s    = gamma[c] * rsqrtf(var + BN_EPS);
        sc[c] = s;
        bs[c] = beta[c] - mean * s;
    }
    __syncthreads();
    const int total4 = N_OUTP * C_OUT / 4;
    for (int i = blockIdx.x * blockDim.x + threadIdx.x; i < total4;
         i += gridDim.x * blockDim.x) {
        const uint2 u = *(const uint2*)(g_Yh + (size_t)i * 4);
        const float2 v01 = __half22float2(*(const __half2*)&u.x);
        const float2 v23 = __half22float2(*(const __half2*)&u.y);
        const int c0 = (i * 4) & 63;
        float4 v;
        v.x = fmaxf(fmaf(v01.x, sc[c0 + 0], bs[c0 + 0]), 0.f);
        v.y = fmaxf(fmaf(v01.y, sc[c0 + 1], bs[c0 + 1]), 0.f);
        v.z = fmaxf(fmaf(v23.x, sc[c0 + 2], bs[c0 + 2]), 0.f);
        v.w = fmaxf(fmaf(v23.y, sc[c0 + 3], bs[c0 + 3]), 0.f);
        ((float4*)out)[i] = v;
    }
}

// ---------------- launch ----------------------------------------------------
extern "C" void kernel_launch(void* const* d_in, const int* in_sizes, int n_in,
                              void* d_out, int out_size)
{
    const float* x       = (const float*)d_in[0];
    const float* weight  = (const float*)d_in[1];
    const float* gamma   = (const float*)d_in[2];
    const float* beta    = (const float*)d_in[3];
    const int*   in_map  = (const int*)d_in[4];
    const int*   out_map = (const int*)d_in[5];
    float*       out     = (float*)d_out;

    cudaFuncSetAttribute(fused_kernel, cudaFuncAttributeMaxDynamicSharedMemorySize,
                         SMEM_FUSED);

    const int wblks = (KOFF * C_IN * C_OUT + 255) / 256;       // 864
    prep_kernel<<<XBLKS + wblks, 256>>>(x, weight);

    {
        dim3 grid((M_PAIRS + PAIRS_BLK - 1) / PAIRS_BLK, KOFF);
        fused_kernel<<<grid, PAIRS_BLK, SMEM_FUSED>>>(in_map, out_map);
    }

    stats_kernel<<<1184, 256>>>();
    normalize_kernel<<<2048, 256>>>(out, gamma, beta);
}